// round 1
// baseline (speedup 1.0000x reference)
#include <cuda_runtime.h>

#define T_STEPS 96
#define BATCH   128
#define ZDIM    32
#define AD      16

// Output section offsets (floats), tuple order:
// mu_filt, sigma_filt, mu_pred, sigma_pred, latent_means, latent_variances, S
#define OFF_MUF   0
#define OFF_SIGF  393216
#define OFF_MUP   12976128
#define OFF_SIGP  13369344
#define OFF_LM    25952256
#define OFF_LV    26738688
#define OFF_S     51904512

__global__ __launch_bounds__(512, 1)
void kalman_kernel(const float* __restrict__ obs,
                   const float* __restrict__ Ag_all,
                   const float* __restrict__ Cg_all,
                   const float* __restrict__ Dg_all,
                   float* __restrict__ out)
{
    const int b    = blockIdx.x;
    const int tid  = threadIdx.x;
    const int lane = tid & 31;
    const int wid  = tid >> 5;       // 0..15

    __shared__ float sig [ZDIM][33];   // carry sigma
    __shared__ float sigz[ZDIM][33];   // filtered sigma
    __shared__ float Tm  [ZDIM][33];   // temp
    __shared__ float Im  [ZDIM][33];   // I - K C
    __shared__ float Am  [ZDIM][33];   // A[b,t+1,0]
    __shared__ float Dm  [ZDIM][33];   // D[b,t+1,0]
    __shared__ float Ct  [AD][33];     // C[b,t]
    __shared__ float CS  [AD][33];     // C @ sigma
    __shared__ float Ssh [AD][17];     // S, then Cholesky L in-place
    __shared__ float Ksh [ZDIM][17];   // Kalman gain [z,a]
    __shared__ float rdiag[AD];
    __shared__ float mu[ZDIM], muz[ZDIM], rv[AD], ov[AD];
    __shared__ float chain[24][ZDIM];  // top-level mean chain

    float* out_muf  = out + OFF_MUF;
    float* out_sigf = out + OFF_SIGF;
    float* out_mup  = out + OFF_MUP;
    float* out_sigp = out + OFF_SIGP;
    float* out_lm   = out + OFF_LM;
    float* out_lv   = out + OFF_LV;
    float* out_S    = out + OFF_S;

    // ---------------- Phase 0: top-level latent chain ----------------
    // chain[0] = mu0 + 0.01 = 0.01 everywhere; jumps use A[b, 4*j, 2]
    if (tid < ZDIM) chain[0][tid] = 0.01f;
    __syncthreads();
    for (int j = 1; j <= 23; ++j) {
        const float* Ag = Ag_all + ((size_t)(b * T_STEPS + 4 * j) * 3 + 2) * 1024;
        {
            int e = tid;        Am[e >> 5][e & 31] = Ag[e];
            e = tid + 512;      Am[e >> 5][e & 31] = Ag[e];
        }
        __syncthreads();
        if (tid < ZDIM) {
            float s = 0.f;
            #pragma unroll
            for (int k = 0; k < ZDIM; ++k) s += Am[tid][k] * chain[j - 1][k];
            chain[j][tid] = s;
        }
        __syncthreads();
    }

    // ---------------- init carry ----------------
    {
        int e = tid;       sig[e >> 5][e & 31] = ((e >> 5) == (e & 31)) ? 20.f : 0.f;
        e = tid + 512;     sig[e >> 5][e & 31] = ((e >> 5) == (e & 31)) ? 20.f : 0.f;
        if (tid < ZDIM) mu[tid] = 0.f;
    }
    __syncthreads();

    // ---------------- main sequential filter ----------------
    for (int t = 0; t < T_STEPS; ++t) {
        // Phase L: load this step's operands
        {
            const float* Cg = Cg_all + (size_t)(b * T_STEPS + t) * 512;
            Ct[wid][lane] = Cg[tid];
            if (tid < AD) ov[tid] = obs[(size_t)(t * BATCH + b) * AD + tid];
            if (t < T_STEPS - 1) {
                const float* Ag = Ag_all + (size_t)((b * T_STEPS + t + 1) * 3) * 1024;
                const float* Dg = Dg_all + (size_t)((b * T_STEPS + t + 1) * 2) * 1024;
                int e = tid;
                Am[e >> 5][e & 31] = Ag[e];  Dm[e >> 5][e & 31] = Dg[e];
                e = tid + 512;
                Am[e >> 5][e & 31] = Ag[e];  Dm[e >> 5][e & 31] = Dg[e];
            }
        }
        __syncthreads();

        // Phase 1: CS = C@sigma (16x32), r = o - C@mu
        {
            float s = 0.f;
            #pragma unroll
            for (int k = 0; k < ZDIM; ++k) s += Ct[wid][k] * sig[k][lane];
            CS[wid][lane] = s;
            if (tid < AD) {
                float rr = ov[tid];
                #pragma unroll
                for (int k = 0; k < ZDIM; ++k) rr -= Ct[tid][k] * mu[k];
                rv[tid] = rr;
            }
        }
        __syncthreads();

        // Phase 2: S = CS@C^T + 0.03 I; write S_tensor
        if (tid < 256) {
            int i = tid >> 4, j = tid & 15;
            float s = (i == j) ? 0.03f : 0.f;
            #pragma unroll
            for (int k = 0; k < ZDIM; ++k) s += CS[i][k] * Ct[j][k];
            Ssh[i][j] = s;
            out_S[(size_t)(t * BATCH + b) * 256 + tid] = s;
        }
        __syncthreads();

        // Phase 3: warp0 = Cholesky + solve S K^T = CS  (K = sigma C^T S^-1)
        //          warps 1..15 overlap: write mu_pred, sigma_pred, latent outs
        if (wid == 0) {
            for (int j = 0; j < AD; ++j) {
                if (lane == j) {
                    float d = sqrtf(Ssh[j][j]);
                    Ssh[j][j] = d;
                    rdiag[j] = 1.f / d;
                }
                __syncwarp();
                float rd = rdiag[j];
                if (lane > j && lane < AD) Ssh[lane][j] *= rd;
                __syncwarp();
                if (lane > j && lane < AD) {
                    float lij = Ssh[lane][j];
                    for (int k = j + 1; k <= lane; ++k) Ssh[lane][k] -= lij * Ssh[k][j];
                }
                __syncwarp();
            }
            // per-lane RHS column c = lane (32 columns of CS)
            float y[AD];
            #pragma unroll
            for (int i = 0; i < AD; ++i) y[i] = CS[i][lane];
            #pragma unroll
            for (int k = 0; k < AD; ++k) {            // forward: L y = c
                float yk = y[k] * rdiag[k];
                y[k] = yk;
                #pragma unroll
                for (int i2 = k + 1; i2 < AD; ++i2) y[i2] -= Ssh[i2][k] * yk;
            }
            #pragma unroll
            for (int k = AD - 1; k >= 0; --k) {       // back: L^T x = y
                float xk = y[k] * rdiag[k];
                y[k] = xk;
                Ksh[lane][k] = xk;
                #pragma unroll
                for (int i2 = 0; i2 < k; ++i2) y[i2] -= Ssh[k][i2] * xk;
            }
        } else {
            int wtid = tid - 32;   // 0..479
            size_t tb = (size_t)(t * BATCH + b);
            if (wtid < ZDIM) out_mup[tb * ZDIM + wtid] = mu[wtid];
            for (int e = wtid; e < 1024; e += 480)
                out_sigp[tb * 1024 + e] = sig[e >> 5][e & 31];
            if (wtid < 64) {
                float v = (wtid < ZDIM) ? 0.f : chain[t >> 2][wtid - ZDIM];
                out_lm[tb * 64 + wtid] = v;
            }
            for (int e = wtid; e < 2048; e += 480) {
                int l = e >> 10, ij = e & 1023;
                int i = ij >> 5, j = ij & 31;
                float v = 0.f;
                if (l == 0) { if (t >= 2 && i == j) v = 0.08f; }
                else        { if (t <  4 && i == j) v = 20.f;  }
                out_lv[tb * 2048 + e] = v;
            }
        }
        __syncthreads();

        // Phase 4: muz = mu + K r ;  Im = I - K C
        {
            if (tid < ZDIM) {
                float s = mu[tid];
                #pragma unroll
                for (int k = 0; k < AD; ++k) s += Ksh[tid][k] * rv[k];
                muz[tid] = s;
            }
            float s0 = (wid == lane) ? 1.f : 0.f;
            float s1 = ((wid + 16) == lane) ? 1.f : 0.f;
            #pragma unroll
            for (int k = 0; k < AD; ++k) {
                float c = Ct[k][lane];
                s0 -= Ksh[wid][k] * c;
                s1 -= Ksh[wid + 16][k] * c;
            }
            Im[wid][lane] = s0;  Im[wid + 16][lane] = s1;
        }
        __syncthreads();

        // Phase 5: Tm = Im @ sig
        {
            float s0 = 0.f, s1 = 0.f;
            #pragma unroll
            for (int k = 0; k < ZDIM; ++k) {
                float c = sig[k][lane];
                s0 += Im[wid][k] * c;
                s1 += Im[wid + 16][k] * c;
            }
            Tm[wid][lane] = s0;  Tm[wid + 16][lane] = s1;
        }
        __syncthreads();

        // Phase 6: sigz = Tm @ Im^T + 0.03 * K K^T   (Joseph form)
        {
            float s0 = 0.f, s1 = 0.f;
            #pragma unroll
            for (int k = 0; k < ZDIM; ++k) {
                float c = Im[lane][k];
                s0 += Tm[wid][k] * c;
                s1 += Tm[wid + 16][k] * c;
            }
            float q0 = 0.f, q1 = 0.f;
            #pragma unroll
            for (int k = 0; k < AD; ++k) {
                float c = Ksh[lane][k];
                q0 += Ksh[wid][k] * c;
                q1 += Ksh[wid + 16][k] * c;
            }
            sigz[wid][lane]      = s0 + 0.03f * q0;
            sigz[wid + 16][lane] = s1 + 0.03f * q1;
        }
        __syncthreads();

        // Phase 7: write filtered outputs; Tm = A @ sigz (for predict)
        {
            size_t tb = (size_t)(t * BATCH + b);
            if (tid < ZDIM) out_muf[tb * ZDIM + tid] = muz[tid];
            out_sigf[tb * 1024 + tid]       = sigz[tid >> 5][tid & 31];
            out_sigf[tb * 1024 + tid + 512] = sigz[(tid + 512) >> 5][tid & 31];
            if (t < T_STEPS - 1) {
                float s0 = 0.f, s1 = 0.f;
                #pragma unroll
                for (int k = 0; k < ZDIM; ++k) {
                    float c = sigz[k][lane];
                    s0 += Am[wid][k] * c;
                    s1 += Am[wid + 16][k] * c;
                }
                Tm[wid][lane] = s0;  Tm[wid + 16][lane] = s1;
            }
        }
        if (t == T_STEPS - 1) break;   // last carry is never output
        __syncthreads();

        // Phase 8: sig = Tm@A^T + 0.08 I + (t<4)*20*D@D^T ; mu = A muz + D m1
        {
            float s0 = 0.f, s1 = 0.f;
            #pragma unroll
            for (int k = 0; k < ZDIM; ++k) {
                float c = Am[lane][k];
                s0 += Tm[wid][k] * c;
                s1 += Tm[wid + 16][k] * c;
            }
            if (t < 4) {   // var1[t] = 20 I for t<4, else 0
                float q0 = 0.f, q1 = 0.f;
                #pragma unroll
                for (int k = 0; k < ZDIM; ++k) {
                    float c = Dm[lane][k];
                    q0 += Dm[wid][k] * c;
                    q1 += Dm[wid + 16][k] * c;
                }
                s0 += 20.f * q0;  s1 += 20.f * q1;
            }
            if (wid == lane)        s0 += 0.08f;
            if (wid + 16 == lane)   s1 += 0.08f;
            sig[wid][lane]      = s0;
            sig[wid + 16][lane] = s1;
            if (tid < ZDIM) {
                float m = 0.f;
                const float* ch = chain[t >> 2];   // mean1[t]
                #pragma unroll
                for (int k = 0; k < ZDIM; ++k)
                    m += Am[tid][k] * muz[k] + Dm[tid][k] * ch[k];
                mu[tid] = m;
            }
        }
        __syncthreads();
    }
}

extern "C" void kernel_launch(void* const* d_in, const int* in_sizes, int n_in,
                              void* d_out, int out_size) {
    const float* obs = (const float*)d_in[0];
    const float* A   = (const float*)d_in[1];
    const float* C   = (const float*)d_in[2];
    const float* D   = (const float*)d_in[3];
    kalman_kernel<<<BATCH, 512>>>(obs, A, C, D, (float*)d_out);
}

// round 2
// speedup vs baseline: 3.0280x; 3.0280x over previous
#include <cuda_runtime.h>

#define T_STEPS 96
#define BATCH   128
#define ZDIM    32
#define AD      16

// Output section offsets (floats), tuple order:
// mu_filt, sigma_filt, mu_pred, sigma_pred, latent_means, latent_variances, S
#define OFF_MUF   0
#define OFF_SIGF  393216
#define OFF_MUP   12976128
#define OFF_SIGP  13369344
#define OFF_LM    25952256
#define OFF_LV    26738688
#define OFF_S     51904512

#define PADZ 36   // 32-wide rows, 144B (16B aligned), conflict-free float4
#define PADA 20   // 16-wide rows, 80B (16B aligned)

__global__ __launch_bounds__(512, 1)
void kalman_kernel(const float* __restrict__ obs,
                   const float* __restrict__ Ag_all,
                   const float* __restrict__ Cg_all,
                   const float* __restrict__ Dg_all,
                   float* __restrict__ out)
{
    const int b    = blockIdx.x;
    const int tid  = threadIdx.x;
    const int lane = tid & 31;
    const int wid  = tid >> 5;       // 0..15

    __shared__ __align__(16) float sigT [ZDIM][PADZ];  // sigT[j][i] = sigma[i][j] (symmetric)
    __shared__ __align__(16) float sigzT[ZDIM][PADZ];  // filtered sigma, transposed
    __shared__ __align__(16) float Tm2  [ZDIM][PADZ];  // A @ sigz, row-major
    __shared__ __align__(16) float Am   [ZDIM][PADZ];  // A[b,t+1,0], row-major
    __shared__ __align__(16) float Dm   [ZDIM][PADZ];  // D[b,t+1,0], row-major
    __shared__ __align__(16) float Ct   [AD][PADZ];    // C[b,t], row-major
    __shared__ __align__(16) float CSr  [AD][PADZ];    // C@sigma, row-major
    __shared__ __align__(16) float CSc  [ZDIM][PADA];  // C@sigma, col-major
    __shared__ __align__(16) float Ksh  [ZDIM][PADA];  // Kalman gain [z][a]
    __shared__ __align__(16) float Sic  [AD][PADA];    // S^-1 (GJ result, symmetric)
    __shared__ __align__(16) float Ssh  [AD][PADA];    // S
    __shared__ __align__(16) float muv[32], muzv[32], rv[16], ov[16];
    __shared__ __align__(16) float chain[24][32];      // top-level mean chain

    float* out_muf  = out + OFF_MUF;
    float* out_sigf = out + OFF_SIGF;
    float* out_mup  = out + OFF_MUP;
    float* out_sigp = out + OFF_SIGP;
    float* out_lm   = out + OFF_LM;
    float* out_lv   = out + OFF_LV;
    float* out_S    = out + OFF_S;

    // ---------------- Prologue: top-level latent chain (3-deep prefetch) ----
    if (tid < 32) chain[0][tid] = 0.01f;
    float2 pf[3];
    #pragma unroll
    for (int s = 0; s < 3; ++s) {
        const float* Ag = Ag_all + ((size_t)(b * T_STEPS + 4 * (s + 1)) * 3 + 2) * 1024;
        pf[s] = make_float2(Ag[tid], Ag[tid + 512]);
    }
    __syncthreads();
    for (int j = 1; j <= 23; ++j) {
        int s = (j - 1) % 3;
        Am[tid >> 5][tid & 31]        = pf[s].x;
        Am[16 + (tid >> 5)][tid & 31] = pf[s].y;
        if (j + 3 <= 23) {
            const float* Ag = Ag_all + ((size_t)(b * T_STEPS + 4 * (j + 3)) * 3 + 2) * 1024;
            pf[s] = make_float2(Ag[tid], Ag[tid + 512]);
        }
        __syncthreads();
        if (tid < 32) {
            const float4* ar = (const float4*)(&Am[tid][0]);
            const float4* ch = (const float4*)(&chain[j - 1][0]);
            float sm = 0.f;
            #pragma unroll
            for (int q = 0; q < 8; ++q) {
                float4 a = ar[q], c = ch[q];
                sm += a.x * c.x + a.y * c.y + a.z * c.z + a.w * c.w;
            }
            chain[j][tid] = sm;
        }
        __syncthreads();
    }

    // ---------------- init state + step-0 operands ----------------
    float rA0, rA1, rD0, rD1, rC = 0.f, rO = 0.f;
    {
        const float* Cg = Cg_all + (size_t)(b * T_STEPS) * 512;
        Ct[tid >> 5][tid & 31] = Cg[tid];
        if (tid < 16) ov[tid] = obs[(size_t)b * AD + tid];
        int e = tid;       sigT[e & 31][e >> 5] = ((e >> 5) == (e & 31)) ? 20.f : 0.f;
        e = tid + 512;     sigT[e & 31][e >> 5] = ((e >> 5) == (e & 31)) ? 20.f : 0.f;
        if (tid < 32) muv[tid] = 0.f;
        // preload A[b,1,0], D[b,1,0] for phase 1 of t=0
        const float* Ag = Ag_all + (size_t)(b * T_STEPS + 1) * 3 * 1024;
        const float* Dg = Dg_all + (size_t)(b * T_STEPS + 1) * 2 * 1024;
        rA0 = Ag[tid]; rA1 = Ag[tid + 512];
        rD0 = Dg[tid]; rD1 = Dg[tid + 512];
    }
    __syncthreads();

    // ---------------- main sequential filter ----------------
    for (int t = 0; t < T_STEPS; ++t) {
        const size_t tb = (size_t)t * BATCH + b;

        // Phase 1: CS = C@sigma; r = o - C@mu; STS next-step A/D
        {
            const float4* cr = (const float4*)(&Ct[wid][0]);
            const float4* sr = (const float4*)(&sigT[lane][0]);
            float s = 0.f;
            #pragma unroll
            for (int q = 0; q < 8; ++q) {
                float4 c = cr[q], g = sr[q];
                s += c.x * g.x + c.y * g.y + c.z * g.z + c.w * g.w;
            }
            CSr[wid][lane] = s;
            CSc[lane][wid] = s;
            Am[tid >> 5][tid & 31]        = rA0;
            Am[16 + (tid >> 5)][tid & 31] = rA1;
            Dm[tid >> 5][tid & 31]        = rD0;
            Dm[16 + (tid >> 5)][tid & 31] = rD1;
            if (tid < 16) {
                const float4* c4 = (const float4*)(&Ct[tid][0]);
                const float4* m4 = (const float4*)muv;
                float rr = ov[tid];
                #pragma unroll
                for (int q = 0; q < 8; ++q) {
                    float4 c = c4[q], m = m4[q];
                    rr -= c.x * m.x + c.y * m.y + c.z * m.z + c.w * m.w;
                }
                rv[tid] = rr;
            }
        }
        __syncthreads();

        // Phase 2: S = CS@C^T + 0.03 I; write S out
        if (tid < 256) {
            int i = tid >> 4, jj = tid & 15;
            const float4* a4 = (const float4*)(&CSr[i][0]);
            const float4* c4 = (const float4*)(&Ct[jj][0]);
            float s = (i == jj) ? 0.03f : 0.f;
            #pragma unroll
            for (int q = 0; q < 8; ++q) {
                float4 a = a4[q], c = c4[q];
                s += a.x * c.x + a.y * c.y + a.z * c.z + a.w * c.w;
            }
            Ssh[i][jj] = s;
            out_S[tb * 256 + tid] = s;
        }
        __syncthreads();

        // Phase 3: prefetch next-step operands; warp0 GJ-inverse of S;
        //          warps 1..15 stream mu_pred/sigma_pred/latent outputs
        if (t + 1 < T_STEPS) {
            rC = Cg_all[(size_t)(b * T_STEPS + t + 1) * 512 + tid];
            if (tid < 16) rO = obs[(size_t)((t + 1) * BATCH + b) * AD + tid];
        }
        if (t + 2 < T_STEPS) {
            const float* Ag = Ag_all + (size_t)(b * T_STEPS + t + 2) * 3 * 1024;
            const float* Dg = Dg_all + (size_t)(b * T_STEPS + t + 2) * 2 * 1024;
            rA0 = Ag[tid]; rA1 = Ag[tid + 512];
            rD0 = Dg[tid]; rD1 = Dg[tid + 512];
        }
        if (wid == 0) {
            // register-resident Gauss-Jordan inverse of SPD 16x16 S
            const int lrow = lane & 15;
            float M[16];
            const float4* sr = (const float4*)(&Ssh[lrow][0]);
            #pragma unroll
            for (int q = 0; q < 4; ++q) {
                float4 v = sr[q];
                M[4 * q + 0] = v.x; M[4 * q + 1] = v.y;
                M[4 * q + 2] = v.z; M[4 * q + 3] = v.w;
            }
            #pragma unroll
            for (int j = 0; j < 16; ++j) {
                float pj = __shfl_sync(0xffffffffu, M[j], j);
                float ip = 1.0f / pj;
                float f  = M[j];
                bool isj = (lrow == j);
                #pragma unroll
                for (int k = 0; k < 16; ++k) {
                    if (k == j) continue;
                    float rj = __shfl_sync(0xffffffffu, M[k], j);
                    float v  = rj * ip;
                    M[k] = isj ? v : fmaf(-f, v, M[k]);
                }
                M[j] = isj ? ip : (-f * ip);
            }
            if (lane < 16) {
                float4* dst = (float4*)(&Sic[lane][0]);
                #pragma unroll
                for (int q = 0; q < 4; ++q)
                    dst[q] = make_float4(M[4 * q], M[4 * q + 1], M[4 * q + 2], M[4 * q + 3]);
            }
        } else {
            int wtid = tid - 32;   // 0..479
            if (wtid < 32) out_mup[tb * 32 + wtid] = muv[wtid];
            for (int e = wtid; e < 1024; e += 480)
                out_sigp[tb * 1024 + e] = sigT[e & 31][e >> 5];
            if (wtid < 64) {
                float v = (wtid < 32) ? 0.f : chain[t >> 2][wtid - 32];
                out_lm[tb * 64 + wtid] = v;
            }
            for (int e = wtid; e < 2048; e += 480) {
                int l = e >> 10, ij = e & 1023;
                int i = ij >> 5, jj = ij & 31;
                float v = 0.f;
                if (l == 0) { if (t >= 2 && i == jj) v = 0.08f; }
                else        { if (t <  4 && i == jj) v = 20.f;  }
                out_lv[tb * 2048 + e] = v;
            }
        }
        __syncthreads();

        // Phase 4: K = CS^T @ Sinv; STS next-step C/obs
        {
            int z = tid >> 4, a = tid & 15;
            const float4* cz = (const float4*)(&CSc[z][0]);
            const float4* sa = (const float4*)(&Sic[a][0]);
            float s = 0.f;
            #pragma unroll
            for (int q = 0; q < 4; ++q) {
                float4 x = cz[q], y = sa[q];
                s += x.x * y.x + x.y * y.y + x.z * y.z + x.w * y.w;
            }
            Ksh[z][a] = s;
            if (t + 1 < T_STEPS) {
                Ct[tid >> 5][tid & 31] = rC;
                if (tid < 16) ov[tid] = rO;
            }
        }
        __syncthreads();

        // Phase 5: sigz = sigma - K@CS (Joseph form is identical for optimal K);
        //          muz = mu + K r
        {
            float s0 = sigT[lane][wid];
            float s1 = sigT[lane][wid + 16];
            const float4* k0 = (const float4*)(&Ksh[wid][0]);
            const float4* k1 = (const float4*)(&Ksh[wid + 16][0]);
            const float4* cj = (const float4*)(&CSc[lane][0]);
            #pragma unroll
            for (int q = 0; q < 4; ++q) {
                float4 c = cj[q], a0 = k0[q], a1 = k1[q];
                s0 -= a0.x * c.x + a0.y * c.y + a0.z * c.z + a0.w * c.w;
                s1 -= a1.x * c.x + a1.y * c.y + a1.z * c.z + a1.w * c.w;
            }
            sigzT[lane][wid]      = s0;
            sigzT[lane][wid + 16] = s1;
            if (tid < 32) {
                const float4* kk = (const float4*)(&Ksh[tid][0]);
                const float4* r4 = (const float4*)rv;
                float m = muv[tid];
                #pragma unroll
                for (int q = 0; q < 4; ++q) {
                    float4 k = kk[q], r = r4[q];
                    m += k.x * r.x + k.y * r.y + k.z * r.z + k.w * r.w;
                }
                muzv[tid] = m;
            }
        }
        __syncthreads();

        // Phase 6: write filtered outputs; Tm2 = A @ sigz
        {
            out_sigf[tb * 1024 + tid]       = sigzT[lane][wid];
            out_sigf[tb * 1024 + 512 + tid] = sigzT[lane][wid + 16];
            if (tid < 32) out_muf[tb * 32 + tid] = muzv[tid];
            if (t < T_STEPS - 1) {
                const float4* a0 = (const float4*)(&Am[wid][0]);
                const float4* a1 = (const float4*)(&Am[wid + 16][0]);
                const float4* zc = (const float4*)(&sigzT[lane][0]);
                float t0 = 0.f, t1 = 0.f;
                #pragma unroll
                for (int q = 0; q < 8; ++q) {
                    float4 z4 = zc[q], x0 = a0[q], x1 = a1[q];
                    t0 += x0.x * z4.x + x0.y * z4.y + x0.z * z4.z + x0.w * z4.w;
                    t1 += x1.x * z4.x + x1.y * z4.y + x1.z * z4.z + x1.w * z4.w;
                }
                Tm2[wid][lane]      = t0;
                Tm2[wid + 16][lane] = t1;
            }
        }
        if (t == T_STEPS - 1) break;
        __syncthreads();

        // Phase 7: sigma' = Tm2@A^T + 0.08 I (+ 20 D@D^T for t<4);
        //          mu' = A muz + D chain[t/4]
        {
            const float4* t0r = (const float4*)(&Tm2[wid][0]);
            const float4* t1r = (const float4*)(&Tm2[wid + 16][0]);
            const float4* aj  = (const float4*)(&Am[lane][0]);
            float s0 = 0.f, s1 = 0.f;
            #pragma unroll
            for (int q = 0; q < 8; ++q) {
                float4 a = aj[q], x0 = t0r[q], x1 = t1r[q];
                s0 += x0.x * a.x + x0.y * a.y + x0.z * a.z + x0.w * a.w;
                s1 += x1.x * a.x + x1.y * a.y + x1.z * a.z + x1.w * a.w;
            }
            if (t < 4) {
                const float4* d0 = (const float4*)(&Dm[wid][0]);
                const float4* d1 = (const float4*)(&Dm[wid + 16][0]);
                const float4* dj = (const float4*)(&Dm[lane][0]);
                float q0 = 0.f, q1 = 0.f;
                #pragma unroll
                for (int q = 0; q < 8; ++q) {
                    float4 d = dj[q], x0 = d0[q], x1 = d1[q];
                    q0 += x0.x * d.x + x0.y * d.y + x0.z * d.z + x0.w * d.w;
                    q1 += x1.x * d.x + x1.y * d.y + x1.z * d.z + x1.w * d.w;
                }
                s0 += 20.f * q0;
                s1 += 20.f * q1;
            }
            if (wid == lane)      s0 += 0.08f;
            if (wid + 16 == lane) s1 += 0.08f;
            sigT[lane][wid]      = s0;
            sigT[lane][wid + 16] = s1;
            if (tid < 32) {
                const float4* ar = (const float4*)(&Am[tid][0]);
                const float4* dr = (const float4*)(&Dm[tid][0]);
                const float4* mz = (const float4*)muzv;
                const float4* ch = (const float4*)(&chain[t >> 2][0]);
                float m = 0.f;
                #pragma unroll
                for (int q = 0; q < 8; ++q) {
                    float4 a = ar[q], d = dr[q], z4 = mz[q], c = ch[q];
                    m += a.x * z4.x + a.y * z4.y + a.z * z4.z + a.w * z4.w;
                    m += d.x * c.x  + d.y * c.y  + d.z * c.z  + d.w * c.w;
                }
                muv[tid] = m;
            }
        }
        __syncthreads();
    }
}

extern "C" void kernel_launch(void* const* d_in, const int* in_sizes, int n_in,
                              void* d_out, int out_size) {
    const float* obs = (const float*)d_in[0];
    const float* A   = (const float*)d_in[1];
    const float* C   = (const float*)d_in[2];
    const float* D   = (const float*)d_in[3];
    kalman_kernel<<<BATCH, 512>>>(obs, A, C, D, (float*)d_out);
}

// round 3
// speedup vs baseline: 3.8708x; 1.2784x over previous
#include <cuda_runtime.h>

#define T_STEPS 96
#define BATCH   128

// Output section offsets (floats), tuple order:
// mu_filt, sigma_filt, mu_pred, sigma_pred, latent_means, latent_variances, S
#define OFF_MUF   0
#define OFF_SIGF  393216
#define OFF_MUP   12976128
#define OFF_SIGP  13369344
#define OFF_LM    25952256
#define OFF_LV    26738688
#define OFF_S     51904512

#define PZ 36   // 32-wide rows padded: 144B, 16B-aligned, conflict-free float4
#define PA 20   // 16-wide rows padded: 80B, 16B-aligned, conflict-free float4

__device__ __forceinline__ float dot4(float4 a, float4 b) {
    return a.x * b.x + a.y * b.y + a.z * b.z + a.w * b.w;
}

__global__ __launch_bounds__(256, 1)
void kalman_kernel(const float* __restrict__ obs,
                   const float* __restrict__ Ag_all,
                   const float* __restrict__ Cg_all,
                   const float* __restrict__ Dg_all,
                   float* __restrict__ out)
{
    const int b    = blockIdx.x;
    const int tid  = threadIdx.x;
    const int lane = tid & 31;
    const int wid  = tid >> 5;       // 0..7

    // symmetric matrices stored once, row-major (row == col by symmetry)
    __shared__ __align__(16) float sigS [32][PZ];  // carry sigma
    __shared__ __align__(16) float sigzS[32][PZ];  // filtered sigma
    __shared__ __align__(16) float TmS  [32][PZ];  // A @ sigz (row-major, not symmetric)
    __shared__ __align__(16) float Am   [32][PZ];  // A[b,t+1,0]
    __shared__ __align__(16) float Dm   [32][PZ];  // D[b,t+1,0]
    __shared__ __align__(16) float Ct   [16][PZ];  // C[b,t]
    __shared__ __align__(16) float CSr  [16][PZ];  // C@sigma row-major
    __shared__ __align__(16) float CSc  [32][PA];  // C@sigma col-major
    __shared__ __align__(16) float Ksh  [32][PA];  // Kalman gain [z][a]
    __shared__ __align__(16) float Sinv [16][PA];  // S^-1
    __shared__ __align__(16) float Ssh  [16][PA];  // S
    __shared__ __align__(16) float muv[32], muzv[32], rv[16], ov[16];
    __shared__ __align__(16) float chain[24][32];  // top-level mean chain

    float* out_muf  = out + OFF_MUF;
    float* out_sigf = out + OFF_SIGF;
    float* out_mup  = out + OFF_MUP;
    float* out_sigp = out + OFF_SIGP;
    float* out_lm   = out + OFF_LM;
    float* out_lv   = out + OFF_LV;
    float* out_S    = out + OFF_S;

    // ---------------- Prologue: top-level latent chain ----------------
    if (tid < 32) chain[0][tid] = 0.01f;
    {
        float4 pf[3];
        #pragma unroll
        for (int s = 0; s < 3; ++s) {
            const float* Ag = Ag_all + ((size_t)(b * T_STEPS + 4 * (s + 1)) * 3 + 2) * 1024;
            pf[s] = *(const float4*)(Ag + tid * 4);
        }
        __syncthreads();
        for (int j = 1; j <= 23; ++j) {
            int s = (j - 1) % 3;
            *(float4*)&Am[tid >> 3][(tid & 7) * 4] = pf[s];
            if (j + 3 <= 23) {
                const float* Ag = Ag_all + ((size_t)(b * T_STEPS + 4 * (j + 3)) * 3 + 2) * 1024;
                pf[s] = *(const float4*)(Ag + tid * 4);
            }
            __syncthreads();
            if (tid < 32) {
                const float4* ar = (const float4*)&Am[tid][0];
                const float4* ch = (const float4*)&chain[j - 1][0];
                float sm = 0.f;
                #pragma unroll
                for (int q = 0; q < 8; ++q) sm += dot4(ar[q], ch[q]);
                chain[j][tid] = sm;
            }
            __syncthreads();
        }
    }

    // ---------------- init state + step-0/1 operands ----------------
    float4 rA, rD, rC = make_float4(0, 0, 0, 0);
    float  rO = 0.f;
    {
        if (tid < 128)
            *(float4*)&Ct[tid >> 3][(tid & 7) * 4] =
                *(const float4*)(Cg_all + (size_t)(b * T_STEPS) * 512 + tid * 4);
        if (tid < 16) ov[tid] = obs[(size_t)b * 16 + tid];
        {
            int row = tid >> 3, c0 = (tid & 7) * 4;
            float4 sv = make_float4(0, 0, 0, 0);
            if (row >= c0 && row < c0 + 4) {
                int d = row - c0;
                sv.x = (d == 0) ? 20.f : sv.x;
                sv.y = (d == 1) ? 20.f : sv.y;
                sv.z = (d == 2) ? 20.f : sv.z;
                sv.w = (d == 3) ? 20.f : sv.w;
            }
            *(float4*)&sigS[row][c0] = sv;
        }
        if (tid < 32) muv[tid] = 0.f;
        rA = *(const float4*)(Ag_all + (size_t)(b * T_STEPS + 1) * 3 * 1024 + tid * 4);
        rD = *(const float4*)(Dg_all + (size_t)(b * T_STEPS + 1) * 2 * 1024 + tid * 4);
    }
    __syncthreads();

    // ---------------- main sequential filter ----------------
    for (int t = 0; t < T_STEPS; ++t) {
        const size_t tb = (size_t)t * BATCH + b;

        // ---- P1: STS A/D[t+1]; prefetch next; CS = C@sigma; r = o - C@mu ----
        {
            int ar2 = tid >> 3, ac = (tid & 7) * 4;
            *(float4*)&Am[ar2][ac] = rA;
            *(float4*)&Dm[ar2][ac] = rD;
            if (t + 2 < T_STEPS) {
                rA = *(const float4*)(Ag_all + (size_t)(b * T_STEPS + t + 2) * 3 * 1024 + tid * 4);
                rD = *(const float4*)(Dg_all + (size_t)(b * T_STEPS + t + 2) * 2 * 1024 + tid * 4);
            }
            if (t + 1 < T_STEPS) {
                if (tid < 128)
                    rC = *(const float4*)(Cg_all + (size_t)(b * T_STEPS + t + 1) * 512 + tid * 4);
                if (tid < 16)
                    rO = obs[(size_t)((t + 1) * BATCH + b) * 16 + tid];
            }
            const float4* sc = (const float4*)&sigS[lane][0];
            const float4* c0 = (const float4*)&Ct[wid][0];
            const float4* c1 = (const float4*)&Ct[wid + 8][0];
            float s0 = 0.f, s1 = 0.f;
            #pragma unroll
            for (int q = 0; q < 8; ++q) {
                float4 g = sc[q];
                s0 += dot4(c0[q], g);
                s1 += dot4(c1[q], g);
            }
            CSr[wid][lane] = s0;      CSr[wid + 8][lane] = s1;
            CSc[lane][wid] = s0;      CSc[lane][wid + 8] = s1;
            if (tid < 16) {
                const float4* c4 = (const float4*)&Ct[tid][0];
                const float4* m4 = (const float4*)muv;
                float rr = ov[tid];
                #pragma unroll
                for (int q = 0; q < 8; ++q) rr -= dot4(c4[q], m4[q]);
                rv[tid] = rr;
            }
        }
        __syncthreads();

        // ---- P2: S = CS@C^T + 0.03 I; write S out ----
        {
            int i = tid >> 4, j = tid & 15;
            const float4* a4 = (const float4*)&CSr[i][0];
            const float4* c4 = (const float4*)&Ct[j][0];
            float s = (i == j) ? 0.03f : 0.f;
            #pragma unroll
            for (int q = 0; q < 8; ++q) s += dot4(a4[q], c4[q]);
            Ssh[i][j] = s;
            out_S[tb * 256 + tid] = s;
        }
        __syncthreads();

        // ---- P3: warp0 GJ-inverse of S; warps 1-7 stream outputs ----
        if (wid == 0) {
            const int lrow = lane & 15;
            float M[16];
            const float4* sr = (const float4*)&Ssh[lrow][0];
            #pragma unroll
            for (int q = 0; q < 4; ++q) {
                float4 v = sr[q];
                M[4 * q + 0] = v.x; M[4 * q + 1] = v.y;
                M[4 * q + 2] = v.z; M[4 * q + 3] = v.w;
            }
            #pragma unroll
            for (int j = 0; j < 16; ++j) {
                float pj = __shfl_sync(0xffffffffu, M[j], j);
                float ip;
                asm("rcp.approx.ftz.f32 %0, %1;" : "=f"(ip) : "f"(pj));
                ip = ip * (2.0f - pj * ip);          // one Newton step
                float f  = M[j];
                bool isj = (lrow == j);
                #pragma unroll
                for (int k = 0; k < 16; ++k) {
                    if (k == j) continue;
                    float rj = __shfl_sync(0xffffffffu, M[k], j);
                    float v  = rj * ip;
                    M[k] = isj ? v : fmaf(-f, v, M[k]);
                }
                M[j] = isj ? ip : (-f * ip);
            }
            if (lane < 16) {
                float4* dst = (float4*)&Sinv[lane][0];
                #pragma unroll
                for (int q = 0; q < 4; ++q)
                    dst[q] = make_float4(M[4 * q], M[4 * q + 1], M[4 * q + 2], M[4 * q + 3]);
            }
        } else {
            int wtid = tid - 32;   // 0..223
            if (wtid < 8)
                *(float4*)(out_mup + tb * 32 + wtid * 4) = ((const float4*)muv)[wtid];
            for (int e4 = wtid; e4 < 256; e4 += 224) {
                float4 v = *(const float4*)&sigS[e4 >> 3][(e4 & 7) * 4];
                *(float4*)(out_sigp + tb * 1024 + e4 * 4) = v;
            }
            if (wtid < 16) {
                float4 v = make_float4(0, 0, 0, 0);
                if (wtid >= 8) v = *(const float4*)&chain[t >> 2][(wtid - 8) * 4];
                *(float4*)(out_lm + tb * 64 + wtid * 4) = v;
            }
            for (int e4 = wtid; e4 < 512; e4 += 224) {
                int e  = e4 * 4;
                int l  = e >> 10, ij = e & 1023;
                int i  = ij >> 5, j0 = ij & 31;
                float dval = (l == 0) ? ((t >= 2) ? 0.08f : 0.f)
                                      : ((t <  4) ? 20.f  : 0.f);
                bool hit = ((i >> 2) == (j0 >> 2));
                float4 v;
                v.x = (hit && (i & 3) == 0) ? dval : 0.f;
                v.y = (hit && (i & 3) == 1) ? dval : 0.f;
                v.z = (hit && (i & 3) == 2) ? dval : 0.f;
                v.w = (hit && (i & 3) == 3) ? dval : 0.f;
                *(float4*)(out_lv + tb * 2048 + e) = v;
            }
        }
        __syncthreads();

        // ---- P4: K = CS^T @ Sinv; STS next-step C/obs ----
        {
            const float4* cz = (const float4*)&CSc[lane][0];
            const float4* i0 = (const float4*)&Sinv[wid][0];
            const float4* i1 = (const float4*)&Sinv[wid + 8][0];
            float s0 = 0.f, s1 = 0.f;
            #pragma unroll
            for (int q = 0; q < 4; ++q) {
                float4 x = cz[q];
                s0 += dot4(x, i0[q]);
                s1 += dot4(x, i1[q]);
            }
            Ksh[lane][wid]     = s0;
            Ksh[lane][wid + 8] = s1;
            if (t + 1 < T_STEPS) {
                if (tid < 128) *(float4*)&Ct[tid >> 3][(tid & 7) * 4] = rC;
                if (tid < 16)  ov[tid] = rO;
            }
        }
        __syncthreads();

        // ---- P5: sigz = sigma - K@CS ; muz = mu + K r ----
        {
            const float4* cj = (const float4*)&CSc[lane][0];
            float acc0 = sigS[lane][wid];
            float acc1 = sigS[lane][wid + 8];
            float acc2 = sigS[lane][wid + 16];
            float acc3 = sigS[lane][wid + 24];
            #pragma unroll
            for (int q = 0; q < 4; ++q) {
                float4 c = cj[q];
                acc0 -= dot4(*(const float4*)&Ksh[wid][4 * q],      c);
                acc1 -= dot4(*(const float4*)&Ksh[wid + 8][4 * q],  c);
                acc2 -= dot4(*(const float4*)&Ksh[wid + 16][4 * q], c);
                acc3 -= dot4(*(const float4*)&Ksh[wid + 24][4 * q], c);
            }
            sigzS[lane][wid]      = acc0;
            sigzS[lane][wid + 8]  = acc1;
            sigzS[lane][wid + 16] = acc2;
            sigzS[lane][wid + 24] = acc3;
            if (tid < 32) {
                const float4* kk = (const float4*)&Ksh[tid][0];
                const float4* r4 = (const float4*)rv;
                float m = muv[tid];
                #pragma unroll
                for (int q = 0; q < 4; ++q) m += dot4(kk[q], r4[q]);
                muzv[tid] = m;
            }
        }
        __syncthreads();

        // ---- P6: write filtered outputs; Tm = A @ sigz ----
        {
            float4 v = *(const float4*)&sigzS[tid >> 3][(tid & 7) * 4];
            *(float4*)(out_sigf + tb * 1024 + tid * 4) = v;
            if (tid < 8)
                *(float4*)(out_muf + tb * 32 + tid * 4) = ((const float4*)muzv)[tid];
            if (t < T_STEPS - 1) {
                const float4* zc = (const float4*)&sigzS[lane][0];
                float a0 = 0.f, a1 = 0.f, a2 = 0.f, a3 = 0.f;
                #pragma unroll
                for (int q = 0; q < 8; ++q) {
                    float4 g = zc[q];
                    a0 += dot4(*(const float4*)&Am[wid][4 * q],      g);
                    a1 += dot4(*(const float4*)&Am[wid + 8][4 * q],  g);
                    a2 += dot4(*(const float4*)&Am[wid + 16][4 * q], g);
                    a3 += dot4(*(const float4*)&Am[wid + 24][4 * q], g);
                }
                TmS[wid][lane]      = a0;
                TmS[wid + 8][lane]  = a1;
                TmS[wid + 16][lane] = a2;
                TmS[wid + 24][lane] = a3;
            }
        }
        if (t == T_STEPS - 1) break;
        __syncthreads();

        // ---- P7: sigma' = Tm@A^T + 0.08 I (+ 20 D@D^T for t<4); mu' ----
        {
            const float4* al = (const float4*)&Am[lane][0];
            float a0 = 0.f, a1 = 0.f, a2 = 0.f, a3 = 0.f;
            #pragma unroll
            for (int q = 0; q < 8; ++q) {
                float4 a = al[q];
                a0 += dot4(*(const float4*)&TmS[wid][4 * q],      a);
                a1 += dot4(*(const float4*)&TmS[wid + 8][4 * q],  a);
                a2 += dot4(*(const float4*)&TmS[wid + 16][4 * q], a);
                a3 += dot4(*(const float4*)&TmS[wid + 24][4 * q], a);
            }
            if (t < 4) {
                const float4* dl = (const float4*)&Dm[lane][0];
                float q0 = 0.f, q1 = 0.f, q2 = 0.f, q3 = 0.f;
                #pragma unroll
                for (int q = 0; q < 8; ++q) {
                    float4 d = dl[q];
                    q0 += dot4(*(const float4*)&Dm[wid][4 * q],      d);
                    q1 += dot4(*(const float4*)&Dm[wid + 8][4 * q],  d);
                    q2 += dot4(*(const float4*)&Dm[wid + 16][4 * q], d);
                    q3 += dot4(*(const float4*)&Dm[wid + 24][4 * q], d);
                }
                a0 += 20.f * q0;  a1 += 20.f * q1;
                a2 += 20.f * q2;  a3 += 20.f * q3;
            }
            if (wid      == lane) a0 += 0.08f;
            if (wid + 8  == lane) a1 += 0.08f;
            if (wid + 16 == lane) a2 += 0.08f;
            if (wid + 24 == lane) a3 += 0.08f;
            sigS[lane][wid]      = a0;
            sigS[lane][wid + 8]  = a1;
            sigS[lane][wid + 16] = a2;
            sigS[lane][wid + 24] = a3;
            if (tid < 32) {
                const float4* ar = (const float4*)&Am[tid][0];
                const float4* dr = (const float4*)&Dm[tid][0];
                const float4* mz = (const float4*)muzv;
                const float4* ch = (const float4*)&chain[t >> 2][0];
                float m = 0.f;
                #pragma unroll
                for (int q = 0; q < 8; ++q)
                    m += dot4(ar[q], mz[q]) + dot4(dr[q], ch[q]);
                muv[tid] = m;
            }
        }
        __syncthreads();
    }
}

extern "C" void kernel_launch(void* const* d_in, const int* in_sizes, int n_in,
                              void* d_out, int out_size) {
    const float* obs = (const float*)d_in[0];
    const float* A   = (const float*)d_in[1];
    const float* C   = (const float*)d_in[2];
    const float* D   = (const float*)d_in[3];
    kalman_kernel<<<BATCH, 256>>>(obs, A, C, D, (float*)d_out);
}

// round 4
// speedup vs baseline: 3.9892x; 1.0306x over previous
#include <cuda_runtime.h>

#define T_STEPS 96
#define BATCH   128

// Output section offsets (floats), tuple order:
// mu_filt, sigma_filt, mu_pred, sigma_pred, latent_means, latent_variances, S
#define OFF_MUF   0
#define OFF_SIGF  393216
#define OFF_MUP   12976128
#define OFF_SIGP  13369344
#define OFF_LM    25952256
#define OFF_LV    26738688
#define OFF_S     51904512

#define PZ 36   // 32-wide rows padded: 144B, 16B-aligned
#define PA 20   // 16-wide rows padded: 80B, 16B-aligned

__device__ __forceinline__ float dot4(float4 a, float4 b) {
    return a.x * b.x + a.y * b.y + a.z * b.z + a.w * b.w;
}

__global__ __launch_bounds__(256, 1)
void kalman_kernel(const float* __restrict__ obs,
                   const float* __restrict__ Ag_all,
                   const float* __restrict__ Cg_all,
                   const float* __restrict__ Dg_all,
                   float* __restrict__ out)
{
    const int tid  = threadIdx.x;

    // ---------------- writer blocks: latent_variances (input-independent) ----
    if (blockIdx.x >= BATCH) {
        float* out_lv = out + OFF_LV;
        int wb = blockIdx.x - BATCH;          // 0..19
        for (int t = 0; t < T_STEPS; ++t) {
            float d0 = (t >= 2) ? 0.08f : 0.f;
            float d1 = (t <  4) ? 20.f  : 0.f;
            float4* dst = (float4*)(out_lv + (size_t)t * BATCH * 2048);
            for (int e4 = wb * 256 + tid; e4 < 65536; e4 += 20 * 256) {
                int v2 = (e4 * 4) & 2047;
                int l  = v2 >> 10;
                int ij = v2 & 1023;
                int i  = ij >> 5, j0 = ij & 31;
                float dv = l ? d1 : d0;
                bool hit = ((i >> 2) == (j0 >> 2));
                float4 v;
                v.x = (hit && (i & 3) == 0) ? dv : 0.f;
                v.y = (hit && (i & 3) == 1) ? dv : 0.f;
                v.z = (hit && (i & 3) == 2) ? dv : 0.f;
                v.w = (hit && (i & 3) == 3) ? dv : 0.f;
                dst[e4] = v;
            }
        }
        return;
    }

    const int b    = blockIdx.x;
    const int lane = tid & 31;
    const int wid  = tid >> 5;       // 0..7

    __shared__ __align__(16) float sigB[2][32][PZ]; // sigma ping-pong (symmetric)
    __shared__ __align__(16) float Ush [32][PZ];    // U = A @ sigma
    __shared__ __align__(16) float Rsh [32][PZ];    // 20*D@D^T (t<4)
    __shared__ __align__(16) float Am  [32][PZ];    // A[b,t+1,0]
    __shared__ __align__(16) float Dm  [32][PZ];    // D[b,t+1,0]
    __shared__ __align__(16) float Ct  [16][PZ];    // C[b,t]
    __shared__ __align__(16) float CSr [16][PZ];    // CS = C@sigma, row-major
    __shared__ __align__(16) float CSc [32][PA];    // W = sigma C^T (rows = z)
    __shared__ __align__(16) float Vsh [32][PA];    // V = A @ W
    __shared__ __align__(16) float Gsh [32][PA];    // G = V @ Sinv
    __shared__ __align__(16) float Ksh [32][PA];    // K = W @ Sinv
    __shared__ __align__(16) float Sinv[16][PA];
    __shared__ __align__(16) float Ssh [16][PA];
    __shared__ __align__(16) float muB[2][32];
    __shared__ __align__(16) float amv[32], dchv[32], rv[16], ov[16];
    __shared__ __align__(16) float chain[24][32];

    float* out_muf  = out + OFF_MUF;
    float* out_sigf = out + OFF_SIGF;
    float* out_mup  = out + OFF_MUP;
    float* out_sigp = out + OFF_SIGP;
    float* out_lm   = out + OFF_LM;
    float* out_S    = out + OFF_S;

    // ---------------- Prologue: top-level latent chain ----------------
    if (tid < 32) chain[0][tid] = 0.01f;
    {
        float4 pf[3];
        #pragma unroll
        for (int s = 0; s < 3; ++s) {
            const float* Ag = Ag_all + ((size_t)(b * T_STEPS + 4 * (s + 1)) * 3 + 2) * 1024;
            pf[s] = *(const float4*)(Ag + tid * 4);
        }
        __syncthreads();
        for (int j = 1; j <= 23; ++j) {
            int s = (j - 1) % 3;
            *(float4*)&Am[tid >> 3][(tid & 7) * 4] = pf[s];
            if (j + 3 <= 23) {
                const float* Ag = Ag_all + ((size_t)(b * T_STEPS + 4 * (j + 3)) * 3 + 2) * 1024;
                pf[s] = *(const float4*)(Ag + tid * 4);
            }
            __syncthreads();
            if (tid < 32) {
                const float4* ar = (const float4*)&Am[tid][0];
                const float4* ch = (const float4*)&chain[j - 1][0];
                float sm = 0.f;
                #pragma unroll
                for (int q = 0; q < 8; ++q) sm += dot4(ar[q], ch[q]);
                chain[j][tid] = sm;
            }
            __syncthreads();
        }
    }

    // ---------------- init state + step-0/1 operands ----------------
    float4 rA, rD, rC = make_float4(0, 0, 0, 0);
    float  rO = 0.f;
    {
        if (tid < 128)
            *(float4*)&Ct[tid >> 3][(tid & 7) * 4] =
                *(const float4*)(Cg_all + (size_t)(b * T_STEPS) * 512 + tid * 4);
        if (tid < 16) ov[tid] = obs[(size_t)b * 16 + tid];
        {
            int row = tid >> 3, c0 = (tid & 7) * 4;
            float4 sv = make_float4(0, 0, 0, 0);
            if (row >= c0 && row < c0 + 4) {
                int d = row - c0;
                sv.x = (d == 0) ? 20.f : 0.f;
                sv.y = (d == 1) ? 20.f : 0.f;
                sv.z = (d == 2) ? 20.f : 0.f;
                sv.w = (d == 3) ? 20.f : 0.f;
            }
            *(float4*)&sigB[0][row][c0] = sv;
        }
        if (tid < 32) muB[0][tid] = 0.f;
        rA = *(const float4*)(Ag_all + (size_t)(b * T_STEPS + 1) * 3 * 1024 + tid * 4);
        rD = *(const float4*)(Dg_all + (size_t)(b * T_STEPS + 1) * 2 * 1024 + tid * 4);
    }
    __syncthreads();

    // ---------------- main sequential filter ----------------
    for (int t = 0; t < T_STEPS; ++t) {
        const size_t tb = (size_t)t * BATCH + b;
        float (*sgc)[PZ] = sigB[t & 1];
        float (*sgn)[PZ] = sigB[(t + 1) & 1];
        float* muc = muB[t & 1];
        float* mun = muB[(t + 1) & 1];

        // ---- P1: STS A/D[t+1]; prefetch; CS = C@sigma; r = o - C@mu ----
        {
            int ar2 = tid >> 3, ac = (tid & 7) * 4;
            *(float4*)&Am[ar2][ac] = rA;
            *(float4*)&Dm[ar2][ac] = rD;
            if (t + 2 < T_STEPS) {
                rA = *(const float4*)(Ag_all + (size_t)(b * T_STEPS + t + 2) * 3 * 1024 + tid * 4);
                rD = *(const float4*)(Dg_all + (size_t)(b * T_STEPS + t + 2) * 2 * 1024 + tid * 4);
            }
            if (t + 1 < T_STEPS) {
                if (tid < 128)
                    rC = *(const float4*)(Cg_all + (size_t)(b * T_STEPS + t + 1) * 512 + tid * 4);
                if (tid < 16)
                    rO = obs[(size_t)((t + 1) * BATCH + b) * 16 + tid];
            }
            const float4* sc = (const float4*)&sgc[lane][0];
            const float4* c0 = (const float4*)&Ct[wid][0];
            const float4* c1 = (const float4*)&Ct[wid + 8][0];
            float s0 = 0.f, s1 = 0.f;
            #pragma unroll
            for (int q = 0; q < 8; ++q) {
                float4 g = sc[q];
                s0 += dot4(c0[q], g);
                s1 += dot4(c1[q], g);
            }
            CSr[wid][lane] = s0;      CSr[wid + 8][lane] = s1;
            CSc[lane][wid] = s0;      CSc[lane][wid + 8] = s1;
            if (tid < 16) {
                const float4* c4 = (const float4*)&Ct[tid][0];
                const float4* m4 = (const float4*)muc;
                float rr = ov[tid];
                #pragma unroll
                for (int q = 0; q < 8; ++q) rr -= dot4(c4[q], m4[q]);
                rv[tid] = rr;
            }
        }
        __syncthreads();

        // ---- P2: S = CS@C^T + 0.03 I; write S out ----
        {
            int i = tid >> 4, j = tid & 15;
            const float4* a4 = (const float4*)&CSr[i][0];
            const float4* c4 = (const float4*)&Ct[j][0];
            float s = (i == j) ? 0.03f : 0.f;
            #pragma unroll
            for (int q = 0; q < 8; ++q) s += dot4(a4[q], c4[q]);
            Ssh[i][j] = s;
            out_S[tb * 256 + tid] = s;
        }
        __syncthreads();

        // ---- P3: warp0 GJ inverse; warps 1-7: U, V, Amu, Dch, R20, streaming ----
        if (wid == 0) {
            const int lrow = lane & 15;
            float M[16];
            const float4* sr = (const float4*)&Ssh[lrow][0];
            #pragma unroll
            for (int q = 0; q < 4; ++q) {
                float4 v = sr[q];
                M[4 * q + 0] = v.x; M[4 * q + 1] = v.y;
                M[4 * q + 2] = v.z; M[4 * q + 3] = v.w;
            }
            #pragma unroll
            for (int j = 0; j < 16; ++j) {
                float pj = __shfl_sync(0xffffffffu, M[j], j);
                float ip;
                asm("rcp.approx.ftz.f32 %0, %1;" : "=f"(ip) : "f"(pj));
                ip = ip * (2.0f - pj * ip);
                float f  = M[j];
                bool isj = (lrow == j);
                #pragma unroll
                for (int kk = 1; kk < 16; ++kk) {
                    int k = (j + kk) & 15;     // k = j+1 first: shortens pivot chain
                    float rj = __shfl_sync(0xffffffffu, M[k], j);
                    float v  = rj * ip;
                    M[k] = isj ? v : fmaf(-f, v, M[k]);
                }
                M[j] = isj ? ip : (-f * ip);
            }
            if (lane < 16) {
                float4* dst = (float4*)&Sinv[lane][0];
                #pragma unroll
                for (int q = 0; q < 4; ++q)
                    dst[q] = make_float4(M[4 * q], M[4 * q + 1], M[4 * q + 2], M[4 * q + 3]);
            }
        } else {
            int ww   = wid - 1;     // 0..6
            int wtid = tid - 32;    // 0..223
            // output streaming (prior state)
            if (wtid < 8)
                *(float4*)(out_mup + tb * 32 + wtid * 4) = ((const float4*)muc)[wtid];
            for (int e4 = wtid; e4 < 256; e4 += 224) {
                float4 v = *(const float4*)&sgc[e4 >> 3][(e4 & 7) * 4];
                *(float4*)(out_sigp + tb * 1024 + e4 * 4) = v;
            }
            if (wtid < 16) {
                float4 v = make_float4(0, 0, 0, 0);
                if (wtid >= 8) v = *(const float4*)&chain[t >> 2][(wtid - 8) * 4];
                *(float4*)(out_lm + tb * 64 + wtid * 4) = v;
            }
            if (t + 1 < T_STEPS) {
                // U = A @ sigma (rows ww + 7m), V = A @ W
                float4 scol[8], wr[8];
                #pragma unroll
                for (int q = 0; q < 8; ++q) scol[q] = ((const float4*)&sgc[lane][0])[q];
                #pragma unroll
                for (int q = 0; q < 8; ++q) wr[q] = ((const float4*)&CSr[lane & 15][0])[q];
                #pragma unroll
                for (int m = 0; m < 5; ++m) {
                    int r = ww + 7 * m;
                    if (r < 32) {
                        const float4* ar = (const float4*)&Am[r][0];
                        float u = 0.f, v = 0.f;
                        #pragma unroll
                        for (int q = 0; q < 8; ++q) {
                            float4 a = ar[q];
                            u += dot4(a, scol[q]);
                            v += dot4(a, wr[q]);
                        }
                        Ush[r][lane] = u;
                        Vsh[r][lane & 15] = v;
                    }
                }
                if (ww == 6) {   // Amu + Dch (warp 7, lightest U load)
                    const float4* al = (const float4*)&Am[lane][0];
                    const float4* dl = (const float4*)&Dm[lane][0];
                    const float4* m4 = (const float4*)muc;
                    const float4* ch = (const float4*)&chain[t >> 2][0];
                    float am = 0.f, dc = 0.f;
                    #pragma unroll
                    for (int q = 0; q < 8; ++q) {
                        am += dot4(al[q], m4[q]);
                        dc += dot4(dl[q], ch[q]);
                    }
                    amv[lane]  = am;
                    dchv[lane] = dc;
                }
                if (t < 4) {     // R20 = 20 * D @ D^T
                    float4 dcol[8];
                    #pragma unroll
                    for (int q = 0; q < 8; ++q) dcol[q] = ((const float4*)&Dm[lane][0])[q];
                    #pragma unroll
                    for (int m = 0; m < 5; ++m) {
                        int r = ww + 7 * m;
                        if (r < 32) {
                            const float4* dr = (const float4*)&Dm[r][0];
                            float s = 0.f;
                            #pragma unroll
                            for (int q = 0; q < 8; ++q) s += dot4(dr[q], dcol[q]);
                            Rsh[r][lane] = 20.f * s;
                        }
                    }
                }
            }
        }
        __syncthreads();

        // ---- P4: K = W@Sinv, G = V@Sinv; STS next C/obs ----
        {
            const float4* i0 = (const float4*)&Sinv[wid][0];
            const float4* i1 = (const float4*)&Sinv[wid + 8][0];
            {
                const float4* cz = (const float4*)&CSc[lane][0];
                float s0 = 0.f, s1 = 0.f;
                #pragma unroll
                for (int q = 0; q < 4; ++q) {
                    float4 x = cz[q];
                    s0 += dot4(x, i0[q]);
                    s1 += dot4(x, i1[q]);
                }
                Ksh[lane][wid]     = s0;
                Ksh[lane][wid + 8] = s1;
            }
            if (t + 1 < T_STEPS) {
                const float4* vz = (const float4*)&Vsh[lane][0];
                float g0 = 0.f, g1 = 0.f;
                #pragma unroll
                for (int q = 0; q < 4; ++q) {
                    float4 x = vz[q];
                    g0 += dot4(x, i0[q]);
                    g1 += dot4(x, i1[q]);
                }
                Gsh[lane][wid]     = g0;
                Gsh[lane][wid + 8] = g1;
                if (tid < 128) *(float4*)&Ct[tid >> 3][(tid & 7) * 4] = rC;
                if (tid < 16)  ov[tid] = rO;
            }
        }
        __syncthreads();

        // ---- P5: sigz -> sigf (registers->GMEM); sigma'/mu' into ping-pong ----
        {
            // filtered covariance: sigz = sigma - K @ W^T, streamed directly
            float4 wl[4];
            #pragma unroll
            for (int q = 0; q < 4; ++q) wl[q] = ((const float4*)&CSc[lane][0])[q];
            #pragma unroll
            for (int ii = 0; ii < 4; ++ii) {
                int i = wid + 8 * ii;
                const float4* kr = (const float4*)&Ksh[i][0];
                float z = sgc[i][lane];
                #pragma unroll
                for (int q = 0; q < 4; ++q) z -= dot4(kr[q], wl[q]);
                out_sigf[tb * 1024 + i * 32 + lane] = z;
            }
            if (tid < 32) {   // mu_filt
                const float4* kk = (const float4*)&Ksh[tid][0];
                const float4* r4 = (const float4*)rv;
                float m = muc[tid];
                #pragma unroll
                for (int q = 0; q < 4; ++q) m += dot4(kk[q], r4[q]);
                out_muf[tb * 32 + tid] = m;
            }
            if (t + 1 < T_STEPS) {
                // sigma' = U A^T - G V^T + 0.08 I (+ R20)
                float4 al[8], vl[4];
                #pragma unroll
                for (int q = 0; q < 8; ++q) al[q] = ((const float4*)&Am[lane][0])[q];
                #pragma unroll
                for (int q = 0; q < 4; ++q) vl[q] = ((const float4*)&Vsh[lane][0])[q];
                #pragma unroll
                for (int ii = 0; ii < 4; ++ii) {
                    int i = wid + 8 * ii;
                    const float4* ur = (const float4*)&Ush[i][0];
                    const float4* gr = (const float4*)&Gsh[i][0];
                    float s = 0.f;
                    #pragma unroll
                    for (int q = 0; q < 8; ++q) s += dot4(ur[q], al[q]);
                    #pragma unroll
                    for (int q = 0; q < 4; ++q) s -= dot4(gr[q], vl[q]);
                    if (i == lane) s += 0.08f;
                    if (t < 4)     s += Rsh[i][lane];
                    sgn[i][lane] = s;
                }
                if (tid >= 32 && tid < 64) {   // mu' = Amu + G r + Dch
                    int l = lane;
                    const float4* gr = (const float4*)&Gsh[l][0];
                    const float4* r4 = (const float4*)rv;
                    float m = amv[l] + dchv[l];
                    #pragma unroll
                    for (int q = 0; q < 4; ++q) m += dot4(gr[q], r4[q]);
                    mun[l] = m;
                }
            }
        }
        __syncthreads();
    }
}

extern "C" void kernel_launch(void* const* d_in, const int* in_sizes, int n_in,
                              void* d_out, int out_size) {
    const float* obs = (const float*)d_in[0];
    const float* A   = (const float*)d_in[1];
    const float* C   = (const float*)d_in[2];
    const float* D   = (const float*)d_in[3];
    kalman_kernel<<<BATCH + 20, 256>>>(obs, A, C, D, (float*)d_out);
}

// round 5
// speedup vs baseline: 4.0613x; 1.0181x over previous
#include <cuda_runtime.h>

#define T_STEPS 96
#define BATCH   128

// Output section offsets (floats), tuple order:
// mu_filt, sigma_filt, mu_pred, sigma_pred, latent_means, latent_variances, S
#define OFF_MUF   0
#define OFF_SIGF  393216
#define OFF_MUP   12976128
#define OFF_SIGP  13369344
#define OFF_LM    25952256
#define OFF_LV    26738688
#define OFF_S     51904512

#define PZ 36   // 32-wide rows padded: 144B, 16B-aligned
#define PA 20   // 16-wide rows padded: 80B, 16B-aligned

__device__ __forceinline__ float dot4(float4 a, float4 b) {
    return a.x * b.x + a.y * b.y + a.z * b.z + a.w * b.w;
}

__global__ __launch_bounds__(256, 1)
void kalman_kernel(const float* __restrict__ obs,
                   const float* __restrict__ Ag_all,
                   const float* __restrict__ Cg_all,
                   const float* __restrict__ Dg_all,
                   float* __restrict__ out)
{
    const int tid  = threadIdx.x;

    // ---------------- writer blocks: latent_variances (input-independent) ----
    if (blockIdx.x >= BATCH) {
        float* out_lv = out + OFF_LV;
        int wb = blockIdx.x - BATCH;          // 0..19
        for (int t = 0; t < T_STEPS; ++t) {
            float d0 = (t >= 2) ? 0.08f : 0.f;
            float d1 = (t <  4) ? 20.f  : 0.f;
            float4* dst = (float4*)(out_lv + (size_t)t * BATCH * 2048);
            for (int e4 = wb * 256 + tid; e4 < 65536; e4 += 20 * 256) {
                int v2 = (e4 * 4) & 2047;
                int l  = v2 >> 10;
                int ij = v2 & 1023;
                int i  = ij >> 5, j0 = ij & 31;
                float dv = l ? d1 : d0;
                bool hit = ((i >> 2) == (j0 >> 2));
                float4 v;
                v.x = (hit && (i & 3) == 0) ? dv : 0.f;
                v.y = (hit && (i & 3) == 1) ? dv : 0.f;
                v.z = (hit && (i & 3) == 2) ? dv : 0.f;
                v.w = (hit && (i & 3) == 3) ? dv : 0.f;
                dst[e4] = v;
            }
        }
        return;
    }

    const int b    = blockIdx.x;
    const int lane = tid & 31;
    const int wid  = tid >> 5;       // 0..7

    __shared__ __align__(16) float sigB[2][32][PZ]; // sigma ping-pong (symmetric)
    __shared__ __align__(16) float Ush [32][PZ];    // U = A @ sigma
    __shared__ __align__(16) float Rsh [32][PZ];    // 20*D@D^T (t<4)
    __shared__ __align__(16) float Am  [32][PZ];    // A[b,t+1,0]
    __shared__ __align__(16) float Dm  [32][PZ];    // D[b,t+1,0]
    __shared__ __align__(16) float Ct  [16][PZ];    // C[b,t]
    __shared__ __align__(16) float CSr [16][PZ];    // CS = C@sigma, row-major
    __shared__ __align__(16) float CSc [32][PA];    // W = sigma C^T (rows = z)
    __shared__ __align__(16) float Vsh [32][PA];    // V = A @ W
    __shared__ __align__(16) float Gsh [32][PA];    // G = V @ Sinv
    __shared__ __align__(16) float Ksh [32][PA];    // K = W @ Sinv
    __shared__ __align__(16) float Sinv[16][PA];
    __shared__ __align__(16) float Ssh [16][PA];
    __shared__ __align__(16) float muB[2][32];
    __shared__ __align__(16) float amv[32], dchv[32], rv[16], ov[16];
    __shared__ __align__(16) float chain[24][32];

    float* out_muf  = out + OFF_MUF;
    float* out_sigf = out + OFF_SIGF;
    float* out_mup  = out + OFF_MUP;
    float* out_sigp = out + OFF_SIGP;
    float* out_lm   = out + OFF_LM;
    float* out_S    = out + OFF_S;

    // ---------------- Prologue: top-level latent chain ----------------
    if (tid < 32) chain[0][tid] = 0.01f;
    {
        float4 pf[3];
        #pragma unroll
        for (int s = 0; s < 3; ++s) {
            const float* Ag = Ag_all + ((size_t)(b * T_STEPS + 4 * (s + 1)) * 3 + 2) * 1024;
            pf[s] = *(const float4*)(Ag + tid * 4);
        }
        __syncthreads();
        for (int j = 1; j <= 23; ++j) {
            int s = (j - 1) % 3;
            *(float4*)&Am[tid >> 3][(tid & 7) * 4] = pf[s];
            if (j + 3 <= 23) {
                const float* Ag = Ag_all + ((size_t)(b * T_STEPS + 4 * (j + 3)) * 3 + 2) * 1024;
                pf[s] = *(const float4*)(Ag + tid * 4);
            }
            __syncthreads();
            if (tid < 32) {
                const float4* ar = (const float4*)&Am[tid][0];
                const float4* ch = (const float4*)&chain[j - 1][0];
                float sm = 0.f;
                #pragma unroll
                for (int q = 0; q < 8; ++q) sm += dot4(ar[q], ch[q]);
                chain[j][tid] = sm;
            }
            __syncthreads();
        }
    }

    // ---------------- init state + t=0 prior outputs + step-0/1 operands ----
    float4 rA, rD, rC = make_float4(0, 0, 0, 0);
    float  rO = 0.f;
    {
        if (tid < 128)
            *(float4*)&Ct[tid >> 3][(tid & 7) * 4] =
                *(const float4*)(Cg_all + (size_t)(b * T_STEPS) * 512 + tid * 4);
        if (tid < 16) ov[tid] = obs[(size_t)b * 16 + tid];
        {
            int row = tid >> 3, c0 = (tid & 7) * 4;
            float4 sv = make_float4(0, 0, 0, 0);
            if (row >= c0 && row < c0 + 4) {
                int d = row - c0;
                sv.x = (d == 0) ? 20.f : 0.f;
                sv.y = (d == 1) ? 20.f : 0.f;
                sv.z = (d == 2) ? 20.f : 0.f;
                sv.w = (d == 3) ? 20.f : 0.f;
            }
            *(float4*)&sigB[0][row][c0] = sv;
            // t=0 priors streamed here (P5 streams t+1 priors from then on)
            *(float4*)(out_sigp + (size_t)b * 1024 + tid * 4) = sv;
        }
        if (tid < 32) muB[0][tid] = 0.f;
        if (tid < 8)
            *(float4*)(out_mup + (size_t)b * 32 + tid * 4) = make_float4(0, 0, 0, 0);
        rA = *(const float4*)(Ag_all + (size_t)(b * T_STEPS + 1) * 3 * 1024 + tid * 4);
        rD = *(const float4*)(Dg_all + (size_t)(b * T_STEPS + 1) * 2 * 1024 + tid * 4);
    }
    __syncthreads();

    // ---------------- main sequential filter ----------------
    for (int t = 0; t < T_STEPS; ++t) {
        const size_t tb = (size_t)t * BATCH + b;
        float (*sgc)[PZ] = sigB[t & 1];
        float (*sgn)[PZ] = sigB[(t + 1) & 1];
        float* muc = muB[t & 1];
        float* mun = muB[(t + 1) & 1];

        float4 scol[8];   // register-cached sigma column `lane` (reused in P3)

        // ---- P1: STS A/D[t+1]; prefetch; CS = C@sigma; r = o - C@mu ----
        {
            int ar2 = tid >> 3, ac = (tid & 7) * 4;
            *(float4*)&Am[ar2][ac] = rA;
            *(float4*)&Dm[ar2][ac] = rD;
            if (t + 2 < T_STEPS) {
                rA = *(const float4*)(Ag_all + (size_t)(b * T_STEPS + t + 2) * 3 * 1024 + tid * 4);
                rD = *(const float4*)(Dg_all + (size_t)(b * T_STEPS + t + 2) * 2 * 1024 + tid * 4);
            }
            if (t + 1 < T_STEPS) {
                if (tid < 128)
                    rC = *(const float4*)(Cg_all + (size_t)(b * T_STEPS + t + 1) * 512 + tid * 4);
                if (tid < 16)
                    rO = obs[(size_t)((t + 1) * BATCH + b) * 16 + tid];
            }
            const float4* sc = (const float4*)&sgc[lane][0];
            const float4* c0 = (const float4*)&Ct[wid][0];
            const float4* c1 = (const float4*)&Ct[wid + 8][0];
            float s0 = 0.f, s1 = 0.f;
            #pragma unroll
            for (int q = 0; q < 8; ++q) {
                float4 g = sc[q];
                scol[q] = g;
                s0 += dot4(c0[q], g);
                s1 += dot4(c1[q], g);
            }
            CSr[wid][lane] = s0;      CSr[wid + 8][lane] = s1;
            CSc[lane][wid] = s0;      CSc[lane][wid + 8] = s1;
            if (tid < 16) {
                const float4* c4 = (const float4*)&Ct[tid][0];
                const float4* m4 = (const float4*)muc;
                float rr = ov[tid];
                #pragma unroll
                for (int q = 0; q < 8; ++q) rr -= dot4(c4[q], m4[q]);
                rv[tid] = rr;
            }
        }
        __syncthreads();

        // ---- P2: S = CS@C^T + 0.03 I; write S out ----
        {
            int i = tid >> 4, j = tid & 15;
            const float4* a4 = (const float4*)&CSr[i][0];
            const float4* c4 = (const float4*)&Ct[j][0];
            float s = (i == j) ? 0.03f : 0.f;
            #pragma unroll
            for (int q = 0; q < 8; ++q) s += dot4(a4[q], c4[q]);
            Ssh[i][j] = s;
            out_S[tb * 256 + tid] = s;
        }
        __syncthreads();

        // ---- P3: warp0 GJ inverse; warps 1-7: U, V, Amu, Dch, R20, lm ----
        if (wid == 0) {
            const int lrow = lane & 15;
            float M[16];
            const float4* sr = (const float4*)&Ssh[lrow][0];
            #pragma unroll
            for (int q = 0; q < 4; ++q) {
                float4 v = sr[q];
                M[4 * q + 0] = v.x; M[4 * q + 1] = v.y;
                M[4 * q + 2] = v.z; M[4 * q + 3] = v.w;
            }
            #pragma unroll
            for (int j = 0; j < 16; ++j) {
                float pj = __shfl_sync(0xffffffffu, M[j], j);
                float ip;
                asm("rcp.approx.ftz.f32 %0, %1;" : "=f"(ip) : "f"(pj));
                float f  = M[j];
                bool isj = (lrow == j);
                #pragma unroll
                for (int kk = 1; kk < 16; ++kk) {
                    int k = (j + kk) & 15;     // k = j+1 first: shortens pivot chain
                    float rj = __shfl_sync(0xffffffffu, M[k], j);
                    float v  = rj * ip;
                    M[k] = isj ? v : fmaf(-f, v, M[k]);
                }
                M[j] = isj ? ip : (-f * ip);
            }
            if (lane < 16) {
                float4* dst = (float4*)&Sinv[lane][0];
                #pragma unroll
                for (int q = 0; q < 4; ++q)
                    dst[q] = make_float4(M[4 * q], M[4 * q + 1], M[4 * q + 2], M[4 * q + 3]);
            }
        } else {
            int ww   = wid - 1;     // 0..6
            int wtid = tid - 32;    // 0..223
            if (wtid < 16) {
                float4 v = make_float4(0, 0, 0, 0);
                if (wtid >= 8) v = *(const float4*)&chain[t >> 2][(wtid - 8) * 4];
                *(float4*)(out_lm + tb * 64 + wtid * 4) = v;
            }
            if (t + 1 < T_STEPS) {
                // U = A @ sigma (rows ww + 7m), V = A @ W
                float4 wr[8];
                #pragma unroll
                for (int q = 0; q < 8; ++q) wr[q] = ((const float4*)&CSr[lane & 15][0])[q];
                #pragma unroll
                for (int m = 0; m < 5; ++m) {
                    int r = ww + 7 * m;
                    if (r < 32) {
                        const float4* ar = (const float4*)&Am[r][0];
                        float u = 0.f, v = 0.f;
                        #pragma unroll
                        for (int q = 0; q < 8; ++q) {
                            float4 a = ar[q];
                            u += dot4(a, scol[q]);
                            v += dot4(a, wr[q]);
                        }
                        Ush[r][lane] = u;
                        Vsh[r][lane & 15] = v;
                    }
                }
                if (ww == 6) {   // Amu + Dch (warp 7, lightest U load)
                    const float4* al7 = (const float4*)&Am[lane][0];
                    const float4* dl7 = (const float4*)&Dm[lane][0];
                    const float4* m4  = (const float4*)muc;
                    const float4* ch  = (const float4*)&chain[t >> 2][0];
                    float am = 0.f, dc = 0.f;
                    #pragma unroll
                    for (int q = 0; q < 8; ++q) {
                        am += dot4(al7[q], m4[q]);
                        dc += dot4(dl7[q], ch[q]);
                    }
                    amv[lane]  = am;
                    dchv[lane] = dc;
                }
                if (t < 4) {     // R20 = 20 * D @ D^T
                    float4 dcol[8];
                    #pragma unroll
                    for (int q = 0; q < 8; ++q) dcol[q] = ((const float4*)&Dm[lane][0])[q];
                    #pragma unroll
                    for (int m = 0; m < 5; ++m) {
                        int r = ww + 7 * m;
                        if (r < 32) {
                            const float4* dr = (const float4*)&Dm[r][0];
                            float s = 0.f;
                            #pragma unroll
                            for (int q = 0; q < 8; ++q) s += dot4(dr[q], dcol[q]);
                            Rsh[r][lane] = 20.f * s;
                        }
                    }
                }
            }
        }
        __syncthreads();

        // ---- P4: K = W@Sinv, G = V@Sinv; load al; STS next C/obs ----
        float4 al[8];   // register-cached A row `lane` for P5
        {
            const float4* i0 = (const float4*)&Sinv[wid][0];
            const float4* i1 = (const float4*)&Sinv[wid + 8][0];
            {
                const float4* cz = (const float4*)&CSc[lane][0];
                float s0 = 0.f, s1 = 0.f;
                #pragma unroll
                for (int q = 0; q < 4; ++q) {
                    float4 x = cz[q];
                    s0 += dot4(x, i0[q]);
                    s1 += dot4(x, i1[q]);
                }
                Ksh[lane][wid]     = s0;
                Ksh[lane][wid + 8] = s1;
            }
            if (t + 1 < T_STEPS) {
                const float4* vz = (const float4*)&Vsh[lane][0];
                float g0 = 0.f, g1 = 0.f;
                #pragma unroll
                for (int q = 0; q < 4; ++q) {
                    float4 x = vz[q];
                    g0 += dot4(x, i0[q]);
                    g1 += dot4(x, i1[q]);
                }
                Gsh[lane][wid]     = g0;
                Gsh[lane][wid + 8] = g1;
                #pragma unroll
                for (int q = 0; q < 8; ++q) al[q] = ((const float4*)&Am[lane][0])[q];
                if (tid < 128) *(float4*)&Ct[tid >> 3][(tid & 7) * 4] = rC;
                if (tid < 16)  ov[tid] = rO;
            }
        }
        __syncthreads();

        // ---- P5: sigz -> sigf; sigma'/mu' -> ping-pong + sigp/mup[t+1] ----
        {
            // filtered covariance: sigz = sigma - K @ W^T, streamed directly
            float4 wl[4];
            #pragma unroll
            for (int q = 0; q < 4; ++q) wl[q] = ((const float4*)&CSc[lane][0])[q];
            #pragma unroll
            for (int ii = 0; ii < 4; ++ii) {
                int i = wid + 8 * ii;
                const float4* kr = (const float4*)&Ksh[i][0];
                float z = sgc[i][lane];
                #pragma unroll
                for (int q = 0; q < 4; ++q) z -= dot4(kr[q], wl[q]);
                out_sigf[tb * 1024 + i * 32 + lane] = z;
            }
            if (tid < 32) {   // mu_filt
                const float4* kk = (const float4*)&Ksh[tid][0];
                const float4* r4 = (const float4*)rv;
                float m = muc[tid];
                #pragma unroll
                for (int q = 0; q < 4; ++q) m += dot4(kk[q], r4[q]);
                out_muf[tb * 32 + tid] = m;
            }
            if (t + 1 < T_STEPS) {
                const size_t tb2 = tb + BATCH;   // (t+1)*BATCH + b
                // sigma' = U A^T - G V^T + 0.08 I (+ R20)
                float4 vl[4];
                #pragma unroll
                for (int q = 0; q < 4; ++q) vl[q] = ((const float4*)&Vsh[lane][0])[q];
                #pragma unroll
                for (int ii = 0; ii < 4; ++ii) {
                    int i = wid + 8 * ii;
                    const float4* ur = (const float4*)&Ush[i][0];
                    const float4* gr = (const float4*)&Gsh[i][0];
                    float s = 0.f;
                    #pragma unroll
                    for (int q = 0; q < 8; ++q) s += dot4(ur[q], al[q]);
                    #pragma unroll
                    for (int q = 0; q < 4; ++q) s -= dot4(gr[q], vl[q]);
                    if (i == lane) s += 0.08f;
                    if (t < 4)     s += Rsh[i][lane];
                    sgn[i][lane] = s;
                    out_sigp[tb2 * 1024 + i * 32 + lane] = s;
                }
                if (tid >= 32 && tid < 64) {   // mu' = Amu + G r + Dch
                    int l = lane;
                    const float4* gr = (const float4*)&Gsh[l][0];
                    const float4* r4 = (const float4*)rv;
                    float m = amv[l] + dchv[l];
                    #pragma unroll
                    for (int q = 0; q < 4; ++q) m += dot4(gr[q], r4[q]);
                    mun[l] = m;
                    out_mup[tb2 * 32 + l] = m;
                }
            }
        }
        __syncthreads();
    }
}

extern "C" void kernel_launch(void* const* d_in, const int* in_sizes, int n_in,
                              void* d_out, int out_size) {
    const float* obs = (const float*)d_in[0];
    const float* A   = (const float*)d_in[1];
    const float* C   = (const float*)d_in[2];
    const float* D   = (const float*)d_in[3];
    kalman_kernel<<<BATCH + 20, 256>>>(obs, A, C, D, (float*)d_out);
}